// round 10
// baseline (speedup 1.0000x reference)
#include <cuda_runtime.h>
#include <cuda_fp16.h>
#include <cstdint>

#define DIMK 768
#define MROWS 4096
#define VCOLS 50257
#define VPAD 50432            // padded vocab = 394 * 128 (even)
#define BM 128
#define BN 128
#define KC 64                 // K elems per stage: 64 half = 128B rows (SW128)
#define NCH (DIMK / KC)       // 12
#define NT2 (VPAD / BN)       // 394 n-tiles
#define NMB (MROWS / BM)      // 32 m-blocks
#define TOT_TILES (NMB * NT2) // 12608
#define CH_ROWS 2             // fixup rows per claim
#define NCHK (BM / CH_ROWS)   // 64 claims per m-block
#define A_STAGE_BYTES (BM * 128)   // 16 KB
#define B_STAGE_BYTES (BN * 128)   // 16 KB
#define STAGE_BYTES (A_STAGE_BYTES + B_STAGE_BYTES)
#define DSMEM (3 * STAGE_BYTES)    // 96 KB
#define NCTA 296                   // 2 per SM, all resident

// Scratch (device globals: allocation-free rule)
__device__ __half g_xn[(size_t)MROWS * DIMK];
__device__ __half g_wn[(size_t)VPAD * DIMK];
__device__ __half g_scr[(size_t)MROWS * VPAD];        // fp16 logits scratch
__device__ float g_partials[(size_t)NT2 * MROWS];     // [ntile][row] transposed
__device__ float g_lse[MROWS];
__device__ int g_tile;
__device__ int g_done[NMB];
__device__ int g_ready[NMB];
__device__ int g_claim[NMB];

__device__ __forceinline__ uint32_t smem_u32(const void* p) {
    uint32_t a;
    asm("{ .reg .u64 t; cvta.to.shared.u64 t, %1; cvt.u32.u64 %0, t; }" : "=r"(a) : "l"(p));
    return a;
}
__device__ __forceinline__ uint32_t swz(uint32_t x) { return x ^ ((x >> 3) & 0x70); }

template <int N>
__device__ __forceinline__ void cpwait() {
    asm volatile("cp.async.wait_group %0;" :: "n"(N) : "memory");
}
__device__ __forceinline__ void cpcommit() {
    asm volatile("cp.async.commit_group;" ::: "memory");
}
__device__ __forceinline__ void cpasync16(uint32_t s, const void* g) {
    asm volatile("cp.async.cg.shared.global [%0], [%1], 16;" :: "r"(s), "l"(g) : "memory");
}
__device__ __forceinline__ void ldm_x4(uint32_t& r0, uint32_t& r1, uint32_t& r2,
                                       uint32_t& r3, uint32_t addr) {
    asm volatile("ldmatrix.sync.aligned.m8n8.x4.shared.b16 {%0,%1,%2,%3}, [%4];"
                 : "=r"(r0), "=r"(r1), "=r"(r2), "=r"(r3) : "r"(addr));
}

// ---------------------------------------------------------------------------
// Reset persistent-kernel state. Runs before gemm each replay.
// ---------------------------------------------------------------------------
__global__ void reset_kernel() {
    if (threadIdx.x == 0) g_tile = 0;
    if (threadIdx.x < NMB) {
        g_done[threadIdx.x] = 0;
        g_ready[threadIdx.x] = 0;
        g_claim[threadIdx.x] = 0;
    }
}

// ---------------------------------------------------------------------------
// Row L2-normalize: 4 rows/block, 64 threads/row, single pass, fp16 out.
// ---------------------------------------------------------------------------
__global__ void __launch_bounds__(256) norm_rows_kernel(const float* __restrict__ x,
                                                        const float* __restrict__ wv) {
    const int tid = threadIdx.x;
    const int sub = tid >> 6;
    const int l64 = tid & 63;
    const int row = blockIdx.x * 4 + sub;

    const float* p;
    __half* q;
    bool zero = false;
    if (row < MROWS) {
        p = x + (size_t)row * DIMK;
        q = g_xn + (size_t)row * DIMK;
    } else {
        int r = row - MROWS;
        q = g_wn + (size_t)r * DIMK;
        p = wv + (size_t)r * DIMK;
        zero = (r >= VCOLS);
    }

    float4 v[3];
    float s = 0.f;
    if (!zero) {
#pragma unroll
        for (int j = 0; j < 3; j++) {
            v[j] = *(const float4*)(p + j * 256 + l64 * 4);
            s += v[j].x * v[j].x + v[j].y * v[j].y + v[j].z * v[j].z + v[j].w * v[j].w;
        }
    } else {
#pragma unroll
        for (int j = 0; j < 3; j++) v[j] = make_float4(0.f, 0.f, 0.f, 0.f);
    }
    for (int o = 16; o; o >>= 1) s += __shfl_xor_sync(0xffffffffu, s, o);
    __shared__ float sm[8];
    if ((tid & 31) == 0) sm[tid >> 5] = s;
    __syncthreads();
    const float tot = sm[sub * 2] + sm[sub * 2 + 1];
    const float scale = zero ? 0.f : (1.f / fmaxf(sqrtf(tot), 1e-12f));

#pragma unroll
    for (int j = 0; j < 3; j++) {
        __half2 h0 = __floats2half2_rn(v[j].x * scale, v[j].y * scale);
        __half2 h1 = __floats2half2_rn(v[j].z * scale, v[j].w * scale);
        uint2 pk = make_uint2(*(uint32_t*)&h0, *(uint32_t*)&h1);
        *(uint2*)(q + j * 256 + l64 * 4) = pk;
    }
}

// ---------------------------------------------------------------------------
// Fixup of CH_ROWS rows by one CTA (128 threads). Pure per-thread (no syncs).
// ---------------------------------------------------------------------------
__device__ void do_fixup(float* __restrict__ out, const float* __restrict__ bias,
                         int base_row, int tid) {
#pragma unroll 1
    for (int r = 0; r < CH_ROWS; r++) {
        const int row = base_row + r;
        const float lse = g_lse[row];
        const __half* ps = g_scr + (size_t)row * VPAD;
        float* po = out + (size_t)row * VCOLS;

        const int head = (4 - (int)(((uintptr_t)po >> 2) & 3)) & 3;
        if (tid < head) po[tid] = __half2float(__ldcs(ps + tid)) - lse + __ldg(bias + tid);
        const int count4 = (VCOLS - head) >> 2;
        const int tail0 = head + count4 * 4;
        if (tid < VCOLS - tail0) {
            const int col = tail0 + tid;
            po[col] = __half2float(__ldcs(ps + col)) - lse + __ldg(bias + col);
        }
        if ((head & 1) == 0) {
#pragma unroll 2
            for (int i = tid; i < count4; i += 128) {
                const int col = head + i * 4;
                float2 a = __half22float2(__ldcs((const __half2*)(ps + col)));
                float2 b = __half22float2(__ldcs((const __half2*)(ps + col + 2)));
                float4 o4;
                o4.x = a.x - lse + __ldg(bias + col);
                o4.y = a.y - lse + __ldg(bias + col + 1);
                o4.z = b.x - lse + __ldg(bias + col + 2);
                o4.w = b.y - lse + __ldg(bias + col + 3);
                *(float4*)(po + col) = o4;
            }
        } else {
#pragma unroll 2
            for (int i = tid; i < count4; i += 128) {
                const int col = head + i * 4;
                float4 o4;
                o4.x = __half2float(__ldcs(ps + col))     - lse + __ldg(bias + col);
                o4.y = __half2float(__ldcs(ps + col + 1)) - lse + __ldg(bias + col + 1);
                o4.z = __half2float(__ldcs(ps + col + 2)) - lse + __ldg(bias + col + 2);
                o4.w = __half2float(__ldcs(ps + col + 3)) - lse + __ldg(bias + col + 3);
                *(float4*)(po + col) = o4;
            }
        }
    }
}

// ---------------------------------------------------------------------------
// Persistent fused GEMM + LSE + overlapped fixup. 296 CTAs (2/SM, resident).
// Tile 128x128, 128 thr (2x2 warps, 64x64 warp tile), 3-stage cp.async.
// ---------------------------------------------------------------------------
__global__ void __launch_bounds__(128, 2) gemm_kernel(float* __restrict__ out,
                                                      const float* __restrict__ bias) {
    extern __shared__ __align__(1024) char smem[];
    __shared__ int s_t, s_old, s_fm, s_fc;

    const int tid = threadIdx.x;
    const int w = tid >> 5, lane = tid & 31;
    const int wm = w >> 1, wn = w & 1;         // 2 x 2 warp grid
    const uint32_t sbase = smem_u32(smem);

    uint32_t aoff[4], boff[4];
#pragma unroll
    for (int mt = 0; mt < 4; mt++)
        aoff[mt] = (uint32_t)(wm * 64 + mt * 16 + (lane & 15)) * 128;
#pragma unroll
    for (int p = 0; p < 4; p++)
        boff[p] = (uint32_t)(wn * 64 + p * 16 + (lane & 7) + ((lane >> 4) & 1) * 8) * 128;
    const uint32_t acol = ((uint32_t)(lane >> 4)) * 16;
    const uint32_t bcol = ((uint32_t)((lane >> 3) & 1)) * 16;
    const int g = lane >> 2, tig = lane & 3;

    for (;;) {
        if (tid == 0) s_t = atomicAdd(&g_tile, 1);
        __syncthreads();
        const int t = s_t;
        if (t >= TOT_TILES) break;
        const int mb = t / NT2;
        const int nt_tile = t - mb * NT2;
        const int m0 = mb * BM;
        const int n0 = nt_tile * BN;

        const __half* Ag = g_xn + (size_t)m0 * DIMK;
        const __half* Bg = g_wn + (size_t)n0 * DIMK;

        auto load_chunk = [&](int slot, int k0) {
            uint32_t sA = sbase + slot * STAGE_BYTES;
            uint32_t sB = sA + A_STAGE_BYTES;
#pragma unroll
            for (int i = 0; i < 8; i++) {
                int s = i * 128 + tid;
                int row = s >> 3, seg = s & 7;
                cpasync16(sA + swz(row * 128 + seg * 16),
                          Ag + (size_t)row * DIMK + k0 + seg * 8);
            }
#pragma unroll
            for (int i = 0; i < 8; i++) {
                int s = i * 128 + tid;
                int row = s >> 3, seg = s & 7;
                cpasync16(sB + swz(row * 128 + seg * 16),
                          Bg + (size_t)row * DIMK + k0 + seg * 8);
            }
            cpcommit();
        };

        float acc[4][8][4];
#pragma unroll
        for (int a = 0; a < 4; a++)
#pragma unroll
            for (int b = 0; b < 8; b++)
#pragma unroll
                for (int c2 = 0; c2 < 4; c2++) acc[a][b][c2] = 0.f;

        uint32_t afr[2][4][4], bfr[2][4][4];

        load_chunk(0, 0);
        load_chunk(1, KC);

#pragma unroll 1
        for (int c = 0; c < NCH; c++) {
            if (c + 2 < NCH) load_chunk((c + 2) % 3, (c + 2) * KC);
            if (c <= NCH - 3) cpwait<2>();
            else if (c == NCH - 2) cpwait<1>();
            else cpwait<0>();
            __syncthreads();

            const uint32_t sA = sbase + (c % 3) * STAGE_BYTES;
            const uint32_t sB = sA + A_STAGE_BYTES;

#pragma unroll
            for (int mt = 0; mt < 4; mt++)
                ldm_x4(afr[0][mt][0], afr[0][mt][1], afr[0][mt][2], afr[0][mt][3],
                       sA + swz(aoff[mt] + acol));
#pragma unroll
            for (int p = 0; p < 4; p++)
                ldm_x4(bfr[0][p][0], bfr[0][p][1], bfr[0][p][2], bfr[0][p][3],
                       sB + swz(boff[p] + bcol));

#pragma unroll
            for (int step = 0; step < KC / 16; step++) {
                const int cur = step & 1;
                if (step < KC / 16 - 1) {
                    const int nxt = cur ^ 1;
                    const uint32_t kb = (uint32_t)(step + 1) * 32;
#pragma unroll
                    for (int mt = 0; mt < 4; mt++)
                        ldm_x4(afr[nxt][mt][0], afr[nxt][mt][1], afr[nxt][mt][2], afr[nxt][mt][3],
                               sA + swz(aoff[mt] + kb + acol));
#pragma unroll
                    for (int p = 0; p < 4; p++)
                        ldm_x4(bfr[nxt][p][0], bfr[nxt][p][1], bfr[nxt][p][2], bfr[nxt][p][3],
                               sB + swz(boff[p] + kb + bcol));
                }
#pragma unroll
                for (int mt = 0; mt < 4; mt++)
#pragma unroll
                    for (int nt = 0; nt < 8; nt++) {
                        const int p = nt >> 1, sub = (nt & 1) * 2;
                        asm volatile(
                            "mma.sync.aligned.m16n8k16.row.col.f32.f16.f16.f32 "
                            "{%0,%1,%2,%3}, {%4,%5,%6,%7}, {%8,%9}, {%0,%1,%2,%3};\n"
                            : "+f"(acc[mt][nt][0]), "+f"(acc[mt][nt][1]),
                              "+f"(acc[mt][nt][2]), "+f"(acc[mt][nt][3])
                            : "r"(afr[cur][mt][0]), "r"(afr[cur][mt][1]),
                              "r"(afr[cur][mt][2]), "r"(afr[cur][mt][3]),
                              "r"(bfr[cur][p][sub]), "r"(bfr[cur][p][sub + 1]));
                    }
            }
            __syncthreads();
        }

        // ---- Epilogue: half2 logits to scratch + exp partials ----
        float* red = (float*)smem;     // 128 rows x 8 slots
#pragma unroll
        for (int mt = 0; mt < 4; mt++)
#pragma unroll
            for (int i = 0; i < 2; i++) {
                float rp = 0.f;
                const int lr = wm * 64 + mt * 16 + g + 8 * i;
                const size_t rb = (size_t)(m0 + lr) * VPAD;
#pragma unroll
                for (int nt = 0; nt < 8; nt++) {
                    const int gcol = n0 + wn * 64 + nt * 8 + 2 * tig;  // even
                    float l0 = acc[mt][nt][i * 2] * 20.f;
                    float l1 = acc[mt][nt][i * 2 + 1] * 20.f;
                    __stcs((__half2*)(g_scr + rb + gcol), __floats2half2_rn(l0, l1));
                    if (gcol < VCOLS)     rp += __expf(l0 - 20.f);
                    if (gcol + 1 < VCOLS) rp += __expf(l1 - 20.f);
                }
                red[lr * 8 + wn * 4 + tig] = rp;
            }
        __syncthreads();
        {
            float s = 0.f;
#pragma unroll
            for (int j = 0; j < 8; j++) s += red[tid * 8 + j];
            g_partials[(size_t)nt_tile * MROWS + m0 + tid] = s;
        }
        __threadfence();
        __syncthreads();
        if (tid == 0) s_old = atomicAdd(&g_done[mb], 1);
        __syncthreads();

        if (s_old == NT2 - 1) {
            // Last finisher: compute this m-block's 128 LSEs (coalesced).
            __threadfence();
            const int row = m0 + tid;
            float s = 0.f;
#pragma unroll 4
            for (int j = 0; j < NT2; j++) s += g_partials[(size_t)j * MROWS + row];
            g_lse[row] = 20.f + logf(s);
            __threadfence();
            __syncthreads();
            if (tid == 0) atomicExch(&g_ready[mb], 1);
        }

        // ---- Opportunistic fixup: one claim per tile ----
        if (tid == 0) {
            s_fm = -1;
            for (int m2 = 0; m2 < NMB; m2++) {
                if (((volatile int*)g_claim)[m2] >= NCHK) continue;
                if (((volatile int*)g_ready)[m2] == 0) continue;
                int c = atomicAdd(&g_claim[m2], 1);
                if (c < NCHK) { s_fm = m2; s_fc = c; break; }
            }
        }
        __syncthreads();
        if (s_fm >= 0) {
            __threadfence();
            do_fixup(out, bias, s_fm * BM + s_fc * CH_ROWS, tid);
        }
        __syncthreads();
    }

    // ---- Drain: finish remaining fixup chunks (progress guaranteed:
    // all CTAs resident; pending tiles are being computed by residents). ----
    for (;;) {
        if (tid == 0) {
            s_fm = -1;
            int pending = 0;
            for (int m2 = 0; m2 < NMB; m2++) {
                if (((volatile int*)g_claim)[m2] >= NCHK) continue;
                pending = 1;
                if (((volatile int*)g_ready)[m2] == 0) continue;
                int c = atomicAdd(&g_claim[m2], 1);
                if (c < NCHK) { s_fm = m2; s_fc = c; break; }
            }
            if (!pending) s_fm = -2;
        }
        __syncthreads();
        if (s_fm == -2) break;
        if (s_fm >= 0) {
            __threadfence();
            do_fixup(out, bias, s_fm * BM + s_fc * CH_ROWS, tid);
        } else {
            __nanosleep(256);
        }
        __syncthreads();
    }
}

extern "C" void kernel_launch(void* const* d_in, const int* in_sizes, int n_in,
                              void* d_out, int out_size) {
    const float* x    = (const float*)d_in[0];  // [2,2048,768]
    const float* wv   = (const float*)d_in[1];  // [50257,768]
    const float* bias = (const float*)d_in[2];  // [50257]
    float* out = (float*)d_out;                 // [2,2048,50257] fp32

    cudaFuncSetAttribute(gemm_kernel, cudaFuncAttributeMaxDynamicSharedMemorySize, DSMEM);

    reset_kernel<<<1, 64>>>();
    norm_rows_kernel<<<(MROWS + VPAD) / 4, 256>>>(x, wv);
    gemm_kernel<<<NCTA, 128, DSMEM>>>(out, bias);
}